// round 7
// baseline (speedup 1.0000x reference)
#include <cuda_runtime.h>
#include <cstdint>

// Problem constants (fixed by the reference):
//   B = 8192 rows
//   slice_input: [B, 16384] f32
//   unmatched:   [B, 256]   f32
//   where:       [B, 1]     4-byte word (int32/float32; word!=0 decodes both,
//                           established empirically R1/R2)
//   output:      [B, 8448]  f32   (256 unmatched ++ 8192 gathered)
// gathered[s*128 + j] = slice[s*256 + j]   (static strided gather)

static constexpr int B_ROWS   = 8192;
static constexpr int D_SLICE  = 16384;
static constexpr int D_UNM    = 256;
static constexpr int D_OUT    = 8448;

// Persistent grid: 148 SMs x 4 CTAs
static constexpr int GRID     = 592;

// ---- 256-bit (v8.f32) global memory ops — Blackwell sm_100+ ----
__device__ __forceinline__ void ldg_v8_cs(float* r, const float* p) {
    asm volatile("ld.global.cs.v8.f32 {%0,%1,%2,%3,%4,%5,%6,%7}, [%8];"
                 : "=f"(r[0]), "=f"(r[1]), "=f"(r[2]), "=f"(r[3]),
                   "=f"(r[4]), "=f"(r[5]), "=f"(r[6]), "=f"(r[7])
                 : "l"(p));
}
__device__ __forceinline__ void stg_v8_cs(float* p, const float* r) {
    asm volatile("st.global.cs.v8.f32 [%0], {%1,%2,%3,%4,%5,%6,%7,%8};"
                 :: "l"(p),
                    "f"(r[0]), "f"(r[1]), "f"(r[2]), "f"(r[3]),
                    "f"(r[4]), "f"(r[5]), "f"(r[6]), "f"(r[7])
                 : "memory");
}

// Persistent CTAs: each CTA loops over rows with stride GRID (concurrent CTAs
// work adjacent rows -> good DRAM locality). Per row: 512 threads,
// gather = 1024 v8-units (2/thread), unmatched = 32 v8-units (threads 0..31).
// v8-unit u: source f32 offset = (u>>4)*256 + (u&15)*8.
__global__ __launch_bounds__(512, 4)
void fused_slice_where_cat_kernel(const uint32_t* __restrict__ mask_words,
                                  const float*    __restrict__ slice_in,
                                  const float*    __restrict__ unmatched,
                                  float*          __restrict__ out)
{
    const int t  = threadIdx.x;
    const int u0 = t;            // v8-unit ids handled by this thread
    const int u1 = t + 512;
    const int src0 = ((u0 >> 4) << 8) + ((u0 & 15) << 3);
    const int src1 = ((u1 >> 4) << 8) + ((u1 & 15) << 3);
    const int dst0 = D_UNM + u0 * 8;
    const int dst1 = D_UNM + u1 * 8;

    for (int row = blockIdx.x; row < B_ROWS; row += GRID) {
        const bool w = mask_words[row] != 0u;

        const float* __restrict__ srow = slice_in  + (size_t)row * D_SLICE;
        const float* __restrict__ urow = unmatched + (size_t)row * D_UNM;
        float*       __restrict__ orow = out       + (size_t)row * D_OUT;

        float r0[8], r1[8], uv[8];

        // batched independent loads
        if (t < 32) ldg_v8_cs(uv, urow + t * 8);

        if (w) {
            ldg_v8_cs(r0, srow + src0);
            ldg_v8_cs(r1, srow + src1);
        } else {
            #pragma unroll
            for (int i = 0; i < 8; i++) { r0[i] = 0.f; r1[i] = 0.f; }
        }

        // batched stores
        if (t < 32) stg_v8_cs(orow + t * 8, uv);
        stg_v8_cs(orow + dst0, r0);
        stg_v8_cs(orow + dst1, r1);
    }
}

extern "C" void kernel_launch(void* const* d_in, const int* in_sizes, int n_in,
                              void* d_out, int out_size)
{
    // Identify inputs by element count (robust against scalar cat_dim /
    // slice_dim inputs and against input-order changes).
    const uint32_t* where_raw = nullptr;
    const float*    slice_in  = nullptr;
    const float*    unmatched = nullptr;

    for (int i = 0; i < n_in; i++) {
        const long long n = in_sizes[i];
        if (n == (long long)B_ROWS) {
            where_raw = (const uint32_t*)d_in[i];
        } else if (n == (long long)B_ROWS * D_SLICE) {
            slice_in = (const float*)d_in[i];
        } else if (n == (long long)B_ROWS * D_UNM) {
            unmatched = (const float*)d_in[i];
        }
    }

    fused_slice_where_cat_kernel<<<GRID, 512>>>(
        where_raw, slice_in, unmatched, (float*)d_out);
}

// round 9
// speedup vs baseline: 1.2353x; 1.2353x over previous
#include <cuda_runtime.h>
#include <cstdint>

// Problem constants (fixed by the reference):
//   B = 8192 rows
//   slice_input: [B, 16384] f32
//   unmatched:   [B, 256]   f32
//   where:       [B, 1]     4-byte word (int32/float32; word!=0 decodes both,
//                           established empirically R1/R2)
//   output:      [B, 8448]  f32   (256 unmatched ++ 8192 gathered)
// gathered[s*128 + j] = slice[s*256 + j]   (static strided gather)

static constexpr int B_ROWS   = 8192;
static constexpr int D_SLICE  = 16384;
static constexpr int D_UNM    = 256;
static constexpr int D_OUT    = 8448;

// ---- 256-bit (v8.f32) global memory ops — Blackwell sm_100+ ----
__device__ __forceinline__ void ldg_v8_cs(float* r, const float* p) {
    asm volatile("ld.global.cs.v8.f32 {%0,%1,%2,%3,%4,%5,%6,%7}, [%8];"
                 : "=f"(r[0]), "=f"(r[1]), "=f"(r[2]), "=f"(r[3]),
                   "=f"(r[4]), "=f"(r[5]), "=f"(r[6]), "=f"(r[7])
                 : "l"(p));
}
__device__ __forceinline__ void stg_v8_cs(float* p, const float* r) {
    asm volatile("st.global.cs.v8.f32 [%0], {%1,%2,%3,%4,%5,%6,%7,%8};"
                 :: "l"(p),
                    "f"(r[0]), "f"(r[1]), "f"(r[2]), "f"(r[3]),
                    "f"(r[4]), "f"(r[5]), "f"(r[6]), "f"(r[7])
                 : "memory");
}

// Two CTAs per row (grid 16384), 256 threads each, finer scheduling grain to
// smooth the bimodal (w=true vs w=false) CTA-runtime spread and the tail wave.
// Row gather = 1024 v8-units; half-row = 512 units -> 2 per thread.
// half==0 CTA also copies the 32 v8-unit unmatched region (threads 0..31).
// v8-unit u: source f32 offset = (u>>4)*256 + (u&15)*8.
__global__ __launch_bounds__(256, 8)
void fused_slice_where_cat_kernel(const uint32_t* __restrict__ mask_words,
                                  const float*    __restrict__ slice_in,
                                  const float*    __restrict__ unmatched,
                                  float*          __restrict__ out)
{
    const int row  = blockIdx.x >> 1;
    const int half = blockIdx.x & 1;
    const int t    = threadIdx.x;
    const bool w   = mask_words[row] != 0u;

    const float* __restrict__ srow = slice_in  + (size_t)row * D_SLICE;
    float*       __restrict__ orow = out       + (size_t)row * D_OUT;

    // v8-unit ids handled by this thread within the full row
    const int u0 = half * 512 + t;
    const int u1 = half * 512 + t + 256;
    const int src0 = ((u0 >> 4) << 8) + ((u0 & 15) << 3);
    const int src1 = ((u1 >> 4) << 8) + ((u1 & 15) << 3);

    float r0[8], r1[8], uv[8];

    // ---- batched independent loads ----
    const bool do_unm = (half == 0) && (t < 32);
    if (do_unm) ldg_v8_cs(uv, unmatched + (size_t)row * D_UNM + t * 8);

    if (w) {
        ldg_v8_cs(r0, srow + src0);
        ldg_v8_cs(r1, srow + src1);
    } else {
        #pragma unroll
        for (int i = 0; i < 8; i++) { r0[i] = 0.f; r1[i] = 0.f; }
    }

    // ---- batched stores ----
    if (do_unm) stg_v8_cs(orow + t * 8, uv);

    float* __restrict__ grow = orow + D_UNM;
    stg_v8_cs(grow + u0 * 8, r0);
    stg_v8_cs(grow + u1 * 8, r1);
}

extern "C" void kernel_launch(void* const* d_in, const int* in_sizes, int n_in,
                              void* d_out, int out_size)
{
    // Identify inputs by element count (robust against scalar cat_dim /
    // slice_dim inputs and against input-order changes).
    const uint32_t* where_raw = nullptr;
    const float*    slice_in  = nullptr;
    const float*    unmatched = nullptr;

    for (int i = 0; i < n_in; i++) {
        const long long n = in_sizes[i];
        if (n == (long long)B_ROWS) {
            where_raw = (const uint32_t*)d_in[i];
        } else if (n == (long long)B_ROWS * D_SLICE) {
            slice_in = (const float*)d_in[i];
        } else if (n == (long long)B_ROWS * D_UNM) {
            unmatched = (const float*)d_in[i];
        }
    }

    fused_slice_where_cat_kernel<<<B_ROWS * 2, 256>>>(
        where_raw, slice_in, unmatched, (float*)d_out);
}